// round 1
// baseline (speedup 1.0000x reference)
#include <cuda_runtime.h>
#include <cuda_bf16.h>
#include <cfloat>
#include <math.h>

// Problem constants
#define BATCH 32
#define HH 256
#define WW 256
#define HW 65536
#define NJ 8
#define KTOP 100
#define NMAPS 288          // 32 hm maps + 256 hm_hp maps
#define CAP 32768          // candidate capacity per map
#define SORTN 4096         // bitonic sort width in topk kernel
#define STAGE 2048         // per-tile staging in nms kernel

// Output layout (concatenated flattened reference outputs, all f32):
// bboxes  [32,100,4]  @ 0
// scores  [32,100,1]  @ 12800
// kps_out [32,100,16] @ 16000
// clses   [32,100,1]  @ 67200
// scale   [32,100,3]  @ 70400
// disp    [32,100,16] @ 80000
// heatkps [32,100,16] @ 131200
#define OFF_BBOX   0
#define OFF_SCORE  12800
#define OFF_KPS    16000
#define OFF_CLS    67200
#define OFF_SCALE  70400
#define OFF_DISP   80000
#define OFF_HEAT   131200

__device__ float g_cand_s[(size_t)NMAPS * CAP];
__device__ int   g_cand_i[(size_t)NMAPS * CAP];
__device__ int   g_cand_n[NMAPS];
__device__ float g_top_s[NMAPS * 128];
__device__ int   g_top_i[NMAPS * 128];

__global__ void k_zero() {
    int i = threadIdx.x;
    if (i < NMAPS) g_cand_n[i] = 0;
}

// Fused sigmoid + 3x3 NMS + candidate compaction.
// grid = (16 row-tiles, 288 maps), block = 256 threads (one per column).
__global__ void k_nms(const float* __restrict__ hm, const float* __restrict__ hm_hp) {
    const int map  = blockIdx.y;
    const int tile = blockIdx.x;
    const int c    = threadIdx.x;

    const float* src = (map < 32) ? (hm + (size_t)map * HW)
                                  : (hm_hp + (size_t)(map - 32) * HW);

    __shared__ float sig[18][WW];
    __shared__ float st_s[STAGE];
    __shared__ int   st_i[STAGE];
    __shared__ int   loc_n;
    __shared__ int   g_base;

    const int base = tile * 16;
    #pragma unroll
    for (int t = 0; t < 18; t++) {
        int row = base - 1 + t;
        float v = -1.0f;                       // below any sigmoid value
        if (row >= 0 && row < HH) {
            float x = src[row * WW + c];
            v = 1.0f / (1.0f + expf(-x));      // sigmoid once per pixel
        }
        sig[t][c] = v;
    }
    if (c == 0) loc_n = 0;
    __syncthreads();

    for (int r = 0; r < 16; r++) {
        float ce = sig[r + 1][c];
        float m = ce, a;
        if (c > 0) {
            a = sig[r][c-1];     if (a > m) m = a;
            a = sig[r+1][c-1];   if (a > m) m = a;
            a = sig[r+2][c-1];   if (a > m) m = a;
        }
        a = sig[r][c];     if (a > m) m = a;
        a = sig[r+2][c];   if (a > m) m = a;
        if (c < WW - 1) {
            a = sig[r][c+1];     if (a > m) m = a;
            a = sig[r+1][c+1];   if (a > m) m = a;
            a = sig[r+2][c+1];   if (a > m) m = a;
        }
        if (ce == m) {   // jax semantics: keep where hmax == heat (sigmoid space)
            int slot = atomicAdd(&loc_n, 1);
            int idx = (base + r) * WW + c;
            if (slot < STAGE) {
                st_s[slot] = ce; st_i[slot] = idx;
            } else {
                int p = atomicAdd(&g_cand_n[map], 1);
                if (p < CAP) {
                    g_cand_s[(size_t)map * CAP + p] = ce;
                    g_cand_i[(size_t)map * CAP + p] = idx;
                }
            }
        }
    }
    __syncthreads();
    int n = min(loc_n, STAGE);
    if (c == 0) g_base = atomicAdd(&g_cand_n[map], n);
    __syncthreads();
    for (int i = c; i < n; i += WW) {
        int p = g_base + i;
        if (p < CAP) {
            g_cand_s[(size_t)map * CAP + p] = st_s[i];
            g_cand_i[(size_t)map * CAP + p] = st_i[i];
        }
    }
}

// Per-map top-100 (sorted desc, jax tie-break by lower HW index).
// grid = 288, block = 1024.
__global__ void k_topk() {
    const int map = blockIdx.x;
    const int tid = threadIdx.x;

    __shared__ int   hist[1024];
    __shared__ float ss[SORTN];
    __shared__ int   si[SORTN];
    __shared__ int   thrbin, cnt2;

    int n = min(g_cand_n[map], CAP);
    const float* cs = g_cand_s + (size_t)map * CAP;
    const int*   ci = g_cand_i + (size_t)map * CAP;

    hist[tid] = 0;
    if (tid == 0) cnt2 = 0;
    __syncthreads();

    // histogram of float bits >> 20 (scores in (0,1) -> monotone key)
    for (int i = tid; i < n; i += 1024) {
        unsigned b = __float_as_uint(cs[i]);
        atomicAdd(&hist[min(b >> 20, 1023u)], 1);
    }
    __syncthreads();
    if (tid == 0) {
        int cum = 0, tb = 0;
        for (int b = 1023; b >= 0; b--) {
            cum += hist[b];
            if (cum >= KTOP) { tb = b; break; }
        }
        thrbin = tb;
    }
    __syncthreads();
    unsigned tb = (unsigned)thrbin;

    for (int i = tid; i < n; i += 1024) {
        float s = cs[i];
        if (min(__float_as_uint(s) >> 20, 1023u) >= tb) {
            int p = atomicAdd(&cnt2, 1);
            if (p < SORTN) { ss[p] = s; si[p] = ci[i]; }
        }
    }
    __syncthreads();
    int m = min(cnt2, SORTN);
    for (int i = tid; i < SORTN; i += 1024) {
        if (i >= m) { ss[i] = -FLT_MAX; si[i] = 0x7FFFFFFF; }
    }

    // bitonic sort, descending by score, ties -> ascending index
    for (int k2 = 2; k2 <= SORTN; k2 <<= 1) {
        for (int j = k2 >> 1; j > 0; j >>= 1) {
            __syncthreads();
            for (int i = tid; i < SORTN; i += 1024) {
                int ixj = i ^ j;
                if (ixj > i) {
                    float s1 = ss[i], s2 = ss[ixj];
                    int   i1 = si[i], i2 = si[ixj];
                    bool pre = (s1 > s2) || (s1 == s2 && i1 <= i2);
                    bool doswap = ((i & k2) == 0) ? (!pre) : pre;
                    if (doswap) {
                        ss[i] = s2; si[i] = i2;
                        ss[ixj] = s1; si[ixj] = i1;
                    }
                }
            }
        }
    }
    __syncthreads();
    if (tid < KTOP) {
        g_top_s[map * 128 + tid] = ss[tid];
        g_top_i[map * 128 + tid] = si[tid];
    }
}

// Center decode: bboxes, scores, clses, obj_scale, kps displacement.
// grid = 32, block = 128.
__global__ void k_center(const float* __restrict__ wh, const float* __restrict__ kps,
                         const float* __restrict__ reg, const float* __restrict__ scale,
                         float* __restrict__ out) {
    const int b = blockIdx.x;
    const int k = threadIdx.x;
    if (k >= KTOP) return;

    float sc = g_top_s[b * 128 + k];
    int ind  = g_top_i[b * 128 + k];
    float ysf = (float)(ind / WW);
    float xsf = (float)(ind % WW);

    const float* regb = reg + (size_t)b * 2 * HW;
    float xr = xsf + regb[ind];
    float yr = ysf + regb[HW + ind];

    const float* whb = wh + (size_t)b * 2 * HW;
    float w0 = whb[ind], w1 = whb[HW + ind];
    float l  = xr - w0 / 2.0f;
    float t  = yr - w1 / 2.0f;
    float rr = xr + w0 / 2.0f;
    float bo = yr + w1 / 2.0f;

    float* ob = out + OFF_BBOX + (size_t)(b * KTOP + k) * 4;
    ob[0] = l; ob[1] = t; ob[2] = rr; ob[3] = bo;

    out[OFF_SCORE + b * KTOP + k] = sc;
    out[OFF_CLS   + b * KTOP + k] = 0.0f;

    const float* scb = scale + (size_t)b * 3 * HW;
    float* os = out + OFF_SCALE + (size_t)(b * KTOP + k) * 3;
    os[0] = scb[ind]; os[1] = scb[HW + ind]; os[2] = scb[2 * HW + ind];

    const float* kb = kps + (size_t)b * 16 * HW;
    float* od = out + OFF_DISP + (size_t)(b * KTOP + k) * 16;
    #pragma unroll
    for (int j = 0; j < NJ; j++) {
        od[2 * j]     = kb[(size_t)(2 * j) * HW + ind] + xsf;
        od[2 * j + 1] = kb[(size_t)(2 * j + 1) * HW + ind] + ysf;
    }
}

// Joint matching: per (b, j) block, 100x100 nearest-neighbor + masks.
// grid = 256, block = 128.
__global__ void k_joint(const float* __restrict__ hp_offset, float* __restrict__ out) {
    const int blk = blockIdx.x;
    const int b = blk / NJ, j = blk % NJ;
    const int tid = threadIdx.x;

    __shared__ float hx[KTOP], hy[KTOP], hs[KTOP];

    const int map = 32 + b * NJ + j;
    if (tid < KTOP) {
        float s = g_top_s[map * 128 + tid];
        int ind = g_top_i[map * 128 + tid];
        float yy = (float)(ind / WW);
        float xx = (float)(ind % WW);
        const float* ob = hp_offset + (size_t)b * 2 * HW;
        xx += ob[ind];
        yy += ob[HW + ind];
        bool m = s > 0.1f;
        hs[tid] = m ? s  : -1.0f;
        hx[tid] = m ? xx : -10000.0f;
        hy[tid] = m ? yy : -10000.0f;
    }
    __syncthreads();
    if (tid >= KTOP) return;
    const int k = tid;

    const float* od = out + OFF_DISP + (size_t)(b * KTOP + k) * 16;
    float px = od[2 * j], py = od[2 * j + 1];

    float bestd = FLT_MAX;
    int bc = 0;
    #pragma unroll 4
    for (int c = 0; c < KTOP; c++) {
        float dx = px - hx[c], dy = py - hy[c];
        float d = sqrtf(dx * dx + dy * dy);
        if (d < bestd) { bestd = d; bc = c; }   // first-index tie-break (argmin)
    }
    float hsg = hs[bc], kx0 = hx[bc], ky0 = hy[bc];

    const float* ob = out + OFF_BBOX + (size_t)(b * KTOP + k) * 4;
    float l = ob[0], t = ob[1], r = ob[2], bo = ob[3];
    float sc = out[OFF_SCORE + b * KTOP + k];
    float diag = fmaxf(bo - t, r - l);

    bool mask = (kx0 < l) || (kx0 > r) || (ky0 < t) || (ky0 > bo) ||
                (hsg < 0.1f) || (bestd > diag * 0.3f);
    float fx = mask ? px : kx0;
    float fy = mask ? py : ky0;
    float* ok = out + OFF_KPS + (size_t)(b * KTOP + k) * 16;
    ok[2 * j] = fx;
    ok[2 * j + 1] = fy;

    bool m2 = (kx0 > 0.8f * l) && (kx0 < 1.2f * r) &&
              (ky0 > 0.8f * t) && (ky0 < 1.2f * bo) &&
              (hsg > 0.1f) && (bestd < diag * 0.5f) && (sc > 0.1f);
    float* oh = out + OFF_HEAT + (size_t)(b * KTOP + k) * 16;
    oh[2 * j]     = m2 ? kx0 : -10000.0f;
    oh[2 * j + 1] = m2 ? ky0 : -10000.0f;
}

extern "C" void kernel_launch(void* const* d_in, const int* in_sizes, int n_in,
                              void* d_out, int out_size) {
    const float* hm        = (const float*)d_in[0];
    const float* wh        = (const float*)d_in[1];
    const float* kps       = (const float*)d_in[2];
    const float* reg       = (const float*)d_in[3];
    const float* hm_hp     = (const float*)d_in[4];
    const float* hp_offset = (const float*)d_in[5];
    const float* scale     = (const float*)d_in[6];
    float* out = (float*)d_out;
    (void)in_sizes; (void)n_in; (void)out_size;

    k_zero<<<1, NMAPS>>>();
    k_nms<<<dim3(16, NMAPS), WW>>>(hm, hm_hp);
    k_topk<<<NMAPS, 1024>>>();
    k_center<<<BATCH, 128>>>(wh, kps, reg, scale, out);
    k_joint<<<BATCH * NJ, 128>>>(hp_offset, out);
}

// round 4
// speedup vs baseline: 1.1098x; 1.1098x over previous
#include <cuda_runtime.h>
#include <cuda_bf16.h>
#include <cfloat>
#include <math.h>

// Problem constants
#define BATCH 32
#define HH 256
#define WW 256
#define HW 65536
#define NJ 8
#define KTOP 100
#define NMAPS 288          // 32 hm maps + 256 hm_hp maps
#define CAP 8192           // candidate capacity per map (~7300 expected)
#define SORTN 512          // bitonic width (survivors after 2-level filter << 512)
#define STAGE 1024         // per-tile staging (expected ~455 survivors/tile)

// Output layout (concatenated flattened reference outputs, all f32):
#define OFF_BBOX   0
#define OFF_SCORE  12800
#define OFF_KPS    16000
#define OFF_CLS    67200
#define OFF_SCALE  70400
#define OFF_DISP   80000
#define OFF_HEAT   131200

__device__ float g_cand_s[(size_t)NMAPS * CAP];
__device__ int   g_cand_i[(size_t)NMAPS * CAP];
__device__ int   g_cand_n[NMAPS];          // zero-init at load; re-zeroed by k_select
__device__ float g_top_s[NMAPS * 128];
__device__ int   g_top_i[NMAPS * 128];

// Monotone uint key from float (total order matching float compare)
__device__ __forceinline__ unsigned fkey(float f) {
    unsigned u = __float_as_uint(f);
    return ((int)u >= 0) ? (u | 0x80000000u) : ~u;
}

// ---------------------------------------------------------------------------
// Sigmoid + 3x3 NMS + candidate compaction (separable max).
// grid = (16 row-tiles, 288 maps), block = 256 threads (one per column).
// Same launch/barrier structure as the R1 version that passed; inner loop is
// separable: horizontal 3-max from the smem sigmoid tile, vertical 3-max via
// per-thread rolling registers. NMS equality in sigmoid space == reference.
// ---------------------------------------------------------------------------
__global__ void k_nms(const float* __restrict__ hm, const float* __restrict__ hm_hp) {
    const int map  = blockIdx.y;
    const int tile = blockIdx.x;
    const int c    = threadIdx.x;

    const float* src = (map < 32) ? (hm + (size_t)map * HW)
                                  : (hm_hp + (size_t)(map - 32) * HW);

    __shared__ float sig[18][WW];
    __shared__ float st_s[STAGE];
    __shared__ int   st_i[STAGE];
    __shared__ int   loc_n;
    __shared__ int   g_base;

    const int base = tile * 16;
    #pragma unroll
    for (int t = 0; t < 18; t++) {
        int row = base - 1 + t;
        float v = -1.0f;                       // below any sigmoid value
        if (row >= 0 && row < HH) {
            float x = src[row * WW + c];
            v = 1.0f / (1.0f + expf(-x));      // sigmoid once per pixel
        }
        sig[t][c] = v;
    }
    if (c == 0) loc_n = 0;
    __syncthreads();

    // Rolling vertical window over horizontal 3-maxes.
    float hm2 = -1.0f, hm1 = -1.0f;
    #pragma unroll
    for (int t = 0; t < 18; t++) {
        float h = sig[t][c];
        if (c > 0)      h = fmaxf(h, sig[t][c - 1]);
        if (c < WW - 1) h = fmaxf(h, sig[t][c + 1]);
        if (t >= 2) {
            // decide output row (base + t - 2); center value = sig[t-1][c]
            float ce = sig[t - 1][c];
            float mx = fmaxf(fmaxf(hm2, hm1), h);
            if (ce == mx) {
                int slot = atomicAdd(&loc_n, 1);
                int idx = (base + t - 2) * WW + c;
                if (slot < STAGE) {
                    st_s[slot] = ce; st_i[slot] = idx;
                } else {
                    int p = atomicAdd(&g_cand_n[map], 1);
                    if (p < CAP) {
                        g_cand_s[(size_t)map * CAP + p] = ce;
                        g_cand_i[(size_t)map * CAP + p] = idx;
                    }
                }
            }
        }
        hm2 = hm1; hm1 = h;
    }
    __syncthreads();
    int n = min(loc_n, STAGE);
    if (c == 0) g_base = atomicAdd(&g_cand_n[map], n);
    __syncthreads();
    for (int i = c; i < n; i += WW) {
        int p = g_base + i;
        if (p < CAP) {
            g_cand_s[(size_t)map * CAP + p] = st_s[i];
            g_cand_i[(size_t)map * CAP + p] = st_i[i];
        }
    }
}

// ---------------------------------------------------------------------------
// Per-map top-100: 2-level 1024-bin histogram on monotone float keys ->
// <=~200 survivors -> 512-wide bitonic (score desc, index asc = jax order).
// grid = 288, block = 1024. Re-zeroes g_cand_n for the next graph replay.
// ---------------------------------------------------------------------------
__global__ void k_select() {
    const int map = blockIdx.x;
    const int tid = threadIdx.x;

    __shared__ int   hist[1024];
    __shared__ int   coarse[32];
    __shared__ float ssort[SORTN];
    __shared__ int   isort[SORTN];
    __shared__ int   s_cnt2, s_t1, s_t2, s_cA;

    const int n = min(g_cand_n[map], CAP);
    const float* cs = g_cand_s + (size_t)map * CAP;
    const int*   ci = g_cand_i + (size_t)map * CAP;

    hist[tid] = 0;
    if (tid == 0) s_cnt2 = 0;
    __syncthreads();                 // all threads have read n
    if (tid == 0) g_cand_n[map] = 0; // reset for next replay

    // Level-1 histogram: key >> 22
    for (int i = tid; i < n; i += 1024)
        atomicAdd(&hist[fkey(cs[i]) >> 22], 1);
    __syncthreads();
    if (tid < 32) {
        int acc = 0;
        for (int j = 0; j < 32; j++) acc += hist[tid * 32 + j];
        coarse[tid] = acc;
    }
    __syncthreads();
    if (tid == 0) {
        int cum = 0, cb = 0;
        for (int b = 31; b >= 0; b--) {
            if (cum + coarse[b] >= KTOP) { cb = b; break; }
            cum += coarse[b];
        }
        int t = cb * 32;
        for (int b = cb * 32 + 31; b >= cb * 32; b--) {
            int h = hist[b];
            if (cum + h >= KTOP) { t = b; break; }
            cum += h; t = b;
        }
        s_t1 = t; s_cA = cum;        // count strictly above bin t
    }
    __syncthreads();
    const unsigned t1 = (unsigned)s_t1;
    const int need2 = max(KTOP - s_cA, 1);

    // Level-2 histogram within bin t1: (key >> 12) & 1023
    hist[tid] = 0;
    __syncthreads();
    for (int i = tid; i < n; i += 1024) {
        unsigned k = fkey(cs[i]);
        if ((k >> 22) == t1) atomicAdd(&hist[(k >> 12) & 1023], 1);
    }
    __syncthreads();
    if (tid < 32) {
        int acc = 0;
        for (int j = 0; j < 32; j++) acc += hist[tid * 32 + j];
        coarse[tid] = acc;
    }
    __syncthreads();
    if (tid == 0) {
        int cum = 0, cb = 0;
        for (int b = 31; b >= 0; b--) {
            if (cum + coarse[b] >= need2) { cb = b; break; }
            cum += coarse[b];
        }
        int t = cb * 32;
        for (int b = cb * 32 + 31; b >= cb * 32; b--) {
            int h = hist[b];
            if (cum + h >= need2) { t = b; break; }
            cum += h; t = b;
        }
        s_t2 = t;
    }
    __syncthreads();
    const unsigned t2 = (unsigned)s_t2;

    // Collect survivors
    for (int i = tid; i < n; i += 1024) {
        unsigned k = fkey(cs[i]);
        unsigned b1 = k >> 22;
        if (b1 > t1 || (b1 == t1 && ((k >> 12) & 1023) >= t2)) {
            int p = atomicAdd(&s_cnt2, 1);
            if (p < SORTN) { ssort[p] = cs[i]; isort[p] = ci[i]; }
        }
    }
    __syncthreads();
    const int m = min(s_cnt2, SORTN);
    if (tid < SORTN && tid >= m) { ssort[tid] = -FLT_MAX; isort[tid] = 0x7FFFFFFF; }

    // Bitonic sort 512 (desc score, asc index on ties)
    for (int k2 = 2; k2 <= SORTN; k2 <<= 1) {
        for (int j = k2 >> 1; j > 0; j >>= 1) {
            __syncthreads();
            if (tid < SORTN) {
                int i = tid, ixj = i ^ j;
                if (ixj > i) {
                    float s1 = ssort[i], s2 = ssort[ixj];
                    int   i1 = isort[i], i2 = isort[ixj];
                    bool pre = (s1 > s2) || (s1 == s2 && i1 <= i2);
                    bool doswap = ((i & k2) == 0) ? (!pre) : pre;
                    if (doswap) {
                        ssort[i] = s2; isort[i] = i2;
                        ssort[ixj] = s1; isort[ixj] = i1;
                    }
                }
            }
        }
    }
    __syncthreads();

    if (tid < KTOP) {
        g_top_s[map * 128 + tid] = ssort[tid];   // already sigmoid values
        g_top_i[map * 128 + tid] = isort[tid];
    }
}

// ---------------------------------------------------------------------------
// Center decode: warp per (b,k) pair; each lane does exactly one gather.
// grid = 400 blocks x 256 threads (8 warps/block -> 3200 pairs).
// ---------------------------------------------------------------------------
__global__ void k_center(const float* __restrict__ wh, const float* __restrict__ kps,
                         const float* __restrict__ reg, const float* __restrict__ scale,
                         float* __restrict__ out) {
    const int pair = blockIdx.x * 8 + (threadIdx.x >> 5);
    const int lane = threadIdx.x & 31;
    if (pair >= BATCH * KTOP) return;
    const int b = pair / KTOP;
    const int k = pair % KTOP;

    const float sc = g_top_s[b * 128 + k];
    const int ind  = g_top_i[b * 128 + k];
    const float ysf = (float)(ind >> 8);
    const float xsf = (float)(ind & 255);

    float g = 0.0f;
    if (lane < 16)       g = kps[((size_t)b * 16 + lane) * HW + ind];
    else if (lane == 16) g = wh[((size_t)b * 2) * HW + ind];
    else if (lane == 17) g = wh[((size_t)b * 2 + 1) * HW + ind];
    else if (lane == 18) g = reg[((size_t)b * 2) * HW + ind];
    else if (lane == 19) g = reg[((size_t)b * 2 + 1) * HW + ind];
    else if (lane < 23)  g = scale[((size_t)b * 3 + (lane - 20)) * HW + ind];

    const unsigned FULL = 0xFFFFFFFFu;
    float w0 = __shfl_sync(FULL, g, 16);
    float w1 = __shfl_sync(FULL, g, 17);
    float r0 = __shfl_sync(FULL, g, 18);
    float r1 = __shfl_sync(FULL, g, 19);
    float xr = xsf + r0, yr = ysf + r1;

    if (lane < 16) {
        out[OFF_DISP + pair * 16 + lane] = g + ((lane & 1) ? ysf : xsf);
    } else if (lane < 20) {
        float bb;
        if      (lane == 16) bb = xr - w0 * 0.5f;
        else if (lane == 17) bb = yr - w1 * 0.5f;
        else if (lane == 18) bb = xr + w0 * 0.5f;
        else                 bb = yr + w1 * 0.5f;
        out[OFF_BBOX + pair * 4 + (lane - 16)] = bb;
    } else if (lane < 23) {
        out[OFF_SCALE + pair * 3 + (lane - 20)] = g;
    } else if (lane == 23) {
        out[OFF_SCORE + pair] = sc;
    } else if (lane == 24) {
        out[OFF_CLS + pair] = 0.0f;
    }
}

// ---------------------------------------------------------------------------
// Joint matching: per (b, j) block, 100x100 nearest-neighbor + masks.
// grid = 256, block = 128.
// ---------------------------------------------------------------------------
__global__ void k_joint(const float* __restrict__ hp_offset, float* __restrict__ out) {
    const int blk = blockIdx.x;
    const int b = blk / NJ, j = blk % NJ;
    const int tid = threadIdx.x;

    __shared__ float hx[KTOP], hy[KTOP], hs[KTOP];

    const int map = 32 + b * NJ + j;
    if (tid < KTOP) {
        float s = g_top_s[map * 128 + tid];
        int ind = g_top_i[map * 128 + tid];
        float yy = (float)(ind >> 8);
        float xx = (float)(ind & 255);
        const float* ob = hp_offset + (size_t)b * 2 * HW;
        xx += ob[ind];
        yy += ob[HW + ind];
        bool m = s > 0.1f;
        hs[tid] = m ? s  : -1.0f;
        hx[tid] = m ? xx : -10000.0f;
        hy[tid] = m ? yy : -10000.0f;
    }
    __syncthreads();
    if (tid >= KTOP) return;
    const int k = tid;

    const float* od = out + OFF_DISP + (size_t)(b * KTOP + k) * 16;
    float px = od[2 * j], py = od[2 * j + 1];

    float bestd = FLT_MAX;
    int bc = 0;
    #pragma unroll 4
    for (int c = 0; c < KTOP; c++) {
        float dx = px - hx[c], dy = py - hy[c];
        float d = sqrtf(dx * dx + dy * dy);
        if (d < bestd) { bestd = d; bc = c; }   // first-index tie-break (argmin)
    }
    float hsg = hs[bc], kx0 = hx[bc], ky0 = hy[bc];

    const float* ob = out + OFF_BBOX + (size_t)(b * KTOP + k) * 4;
    float l = ob[0], t = ob[1], r = ob[2], bo = ob[3];
    float sc = out[OFF_SCORE + b * KTOP + k];
    float diag = fmaxf(bo - t, r - l);

    bool mask = (kx0 < l) || (kx0 > r) || (ky0 < t) || (ky0 > bo) ||
                (hsg < 0.1f) || (bestd > diag * 0.3f);
    float fx = mask ? px : kx0;
    float fy = mask ? py : ky0;
    float* ok = out + OFF_KPS + (size_t)(b * KTOP + k) * 16;
    ok[2 * j] = fx;
    ok[2 * j + 1] = fy;

    bool m2 = (kx0 > 0.8f * l) && (kx0 < 1.2f * r) &&
              (ky0 > 0.8f * t) && (ky0 < 1.2f * bo) &&
              (hsg > 0.1f) && (bestd < diag * 0.5f) && (sc > 0.1f);
    float* oh = out + OFF_HEAT + (size_t)(b * KTOP + k) * 16;
    oh[2 * j]     = m2 ? kx0 : -10000.0f;
    oh[2 * j + 1] = m2 ? ky0 : -10000.0f;
}

extern "C" void kernel_launch(void* const* d_in, const int* in_sizes, int n_in,
                              void* d_out, int out_size) {
    const float* hm        = (const float*)d_in[0];
    const float* wh        = (const float*)d_in[1];
    const float* kps       = (const float*)d_in[2];
    const float* reg       = (const float*)d_in[3];
    const float* hm_hp     = (const float*)d_in[4];
    const float* hp_offset = (const float*)d_in[5];
    const float* scale     = (const float*)d_in[6];
    float* out = (float*)d_out;
    (void)in_sizes; (void)n_in; (void)out_size;

    k_nms<<<dim3(16, NMAPS), WW>>>(hm, hm_hp);
    k_select<<<NMAPS, 1024>>>();
    k_center<<<(BATCH * KTOP + 7) / 8, 256>>>(wh, kps, reg, scale, out);
    k_joint<<<BATCH * NJ, 128>>>(hp_offset, out);
}

// round 5
// speedup vs baseline: 1.8560x; 1.6723x over previous
#include <cuda_runtime.h>
#include <cuda_bf16.h>
#include <cfloat>
#include <math.h>

// Problem constants
#define BATCH 32
#define HH 256
#define WW 256
#define HW 65536
#define NJ 8
#define KTOP 100
#define SELN 110           // selection margin (pool includes rank-100 boundary ties)
#define NMAPS 288          // 32 hm maps + 256 hm_hp maps
#define CAP 8192           // candidate capacity per map (~7300 expected)
#define SORTN 512          // bitonic width
#define STAGE 1024         // per-tile staging (expected ~455 survivors/tile)

// Output layout (concatenated flattened reference outputs, all f32):
#define OFF_BBOX   0
#define OFF_SCORE  12800
#define OFF_KPS    16000
#define OFF_CLS    67200
#define OFF_SCALE  70400
#define OFF_DISP   80000
#define OFF_HEAT   131200

__device__ float g_cand_s[(size_t)NMAPS * CAP];   // raw heat values
__device__ int   g_cand_i[(size_t)NMAPS * CAP];
__device__ int   g_cand_n[NMAPS];                 // zero-init; re-zeroed by k_select
__device__ float g_top_s[NMAPS * 128];            // sigmoid scores
__device__ int   g_top_i[NMAPS * 128];

__device__ __forceinline__ float sigmoidf(float x) {
    return 1.0f / (1.0f + expf(-x));
}

// Monotone uint key from float (total order matching float compare)
__device__ __forceinline__ unsigned fkey(float f) {
    unsigned u = __float_as_uint(f);
    return ((int)u >= 0) ? (u | 0x80000000u) : ~u;
}

// ---------------------------------------------------------------------------
// RAW-space 3x3 NMS + candidate compaction. NO dense sigmoid.
// grid = (16 row-tiles, 288 maps), block = 256 threads (one per column).
// Keep condition equivalent to reference's sigmoid-space hmax==heat:
//   raw ce==mx  (monotone sigmoid => sigmoid equal), OR
//   mx-ce tiny AND sigmoid(ce)==sigmoid(mx)  (rounding-tie fallback, rare).
// ---------------------------------------------------------------------------
__global__ void k_nms(const float* __restrict__ hm, const float* __restrict__ hm_hp) {
    const int map  = blockIdx.y;
    const int tile = blockIdx.x;
    const int c    = threadIdx.x;

    const float* src = (map < 32) ? (hm + (size_t)map * HW)
                                  : (hm_hp + (size_t)(map - 32) * HW);

    __shared__ float raw[18][WW];
    __shared__ float st_s[STAGE];
    __shared__ int   st_i[STAGE];
    __shared__ int   loc_n;
    __shared__ int   g_base;

    const int base = tile * 16;
    #pragma unroll
    for (int t = 0; t < 18; t++) {
        int row = base - 1 + t;
        float v = -FLT_MAX;
        if (row >= 0 && row < HH) v = src[row * WW + c];
        raw[t][c] = v;
    }
    if (c == 0) loc_n = 0;
    __syncthreads();

    // Rolling vertical window over horizontal 3-maxes.
    float hm2 = -FLT_MAX, hm1 = -FLT_MAX;
    #pragma unroll
    for (int t = 0; t < 18; t++) {
        float h = raw[t][c];
        if (c > 0)      h = fmaxf(h, raw[t][c - 1]);
        if (c < WW - 1) h = fmaxf(h, raw[t][c + 1]);
        if (t >= 2) {
            float ce = raw[t - 1][c];
            float mx = fmaxf(fmaxf(hm2, hm1), h);
            bool keep = (ce == mx);
            if (!keep && (mx - ce) < 1e-4f) {
                // sigmoid rounding may tie distinct raws; exact reference check
                keep = (sigmoidf(ce) == sigmoidf(mx));
            }
            if (keep) {
                int slot = atomicAdd(&loc_n, 1);
                int idx = (base + t - 2) * WW + c;
                if (slot < STAGE) {
                    st_s[slot] = ce; st_i[slot] = idx;
                } else {
                    int p = atomicAdd(&g_cand_n[map], 1);
                    if (p < CAP) {
                        g_cand_s[(size_t)map * CAP + p] = ce;
                        g_cand_i[(size_t)map * CAP + p] = idx;
                    }
                }
            }
        }
        hm2 = hm1; hm1 = h;
    }
    __syncthreads();
    int n = min(loc_n, STAGE);
    if (c == 0) g_base = atomicAdd(&g_cand_n[map], n);
    __syncthreads();
    for (int i = c; i < n; i += WW) {
        int p = g_base + i;
        if (p < CAP) {
            g_cand_s[(size_t)map * CAP + p] = st_s[i];
            g_cand_i[(size_t)map * CAP + p] = st_i[i];
        }
    }
}

// ---------------------------------------------------------------------------
// Per-map top-100: 2-level 1024-bin histogram on RAW keys (monotone => same
// order as sigmoid), margin SELN=110 -> pool <= ~200 -> sigmoid pool ->
// 512-wide bitonic by (sigmoid desc, index asc) = reference stable top_k.
// grid = 288, block = 1024. Re-zeroes g_cand_n for the next graph replay.
// ---------------------------------------------------------------------------
__global__ void k_select() {
    const int map = blockIdx.x;
    const int tid = threadIdx.x;

    __shared__ int   hist[1024];
    __shared__ int   coarse[32];
    __shared__ float ssort[SORTN];
    __shared__ int   isort[SORTN];
    __shared__ int   s_cnt2, s_t1, s_t2, s_cA;

    const int n = min(g_cand_n[map], CAP);
    const float* cs = g_cand_s + (size_t)map * CAP;
    const int*   ci = g_cand_i + (size_t)map * CAP;

    hist[tid] = 0;
    if (tid == 0) s_cnt2 = 0;
    __syncthreads();                 // all threads have read n
    if (tid == 0) g_cand_n[map] = 0; // reset for next replay

    // Level-1 histogram: key >> 22
    for (int i = tid; i < n; i += 1024)
        atomicAdd(&hist[fkey(cs[i]) >> 22], 1);
    __syncthreads();
    if (tid < 32) {
        int acc = 0;
        for (int j = 0; j < 32; j++) acc += hist[tid * 32 + j];
        coarse[tid] = acc;
    }
    __syncthreads();
    if (tid == 0) {
        int cum = 0, cb = 0;
        for (int b = 31; b >= 0; b--) {
            if (cum + coarse[b] >= SELN) { cb = b; break; }
            cum += coarse[b];
        }
        int t = cb * 32;
        for (int b = cb * 32 + 31; b >= cb * 32; b--) {
            int h = hist[b];
            if (cum + h >= SELN) { t = b; break; }
            cum += h; t = b;
        }
        s_t1 = t; s_cA = cum;        // count strictly above bin t
    }
    __syncthreads();
    const unsigned t1 = (unsigned)s_t1;
    const int need2 = max(SELN - s_cA, 1);

    // Level-2 histogram within bin t1: (key >> 12) & 1023
    hist[tid] = 0;
    __syncthreads();
    for (int i = tid; i < n; i += 1024) {
        unsigned k = fkey(cs[i]);
        if ((k >> 22) == t1) atomicAdd(&hist[(k >> 12) & 1023], 1);
    }
    __syncthreads();
    if (tid < 32) {
        int acc = 0;
        for (int j = 0; j < 32; j++) acc += hist[tid * 32 + j];
        coarse[tid] = acc;
    }
    __syncthreads();
    if (tid == 0) {
        int cum = 0, cb = 0;
        for (int b = 31; b >= 0; b--) {
            if (cum + coarse[b] >= need2) { cb = b; break; }
            cum += coarse[b];
        }
        int t = cb * 32;
        for (int b = cb * 32 + 31; b >= cb * 32; b--) {
            int h = hist[b];
            if (cum + h >= need2) { t = b; break; }
            cum += h; t = b;
        }
        s_t2 = t;
    }
    __syncthreads();
    const unsigned t2 = (unsigned)s_t2;

    // Collect survivors; sigmoid applied here (pool only, <=512 per map)
    for (int i = tid; i < n; i += 1024) {
        unsigned k = fkey(cs[i]);
        unsigned b1 = k >> 22;
        if (b1 > t1 || (b1 == t1 && ((k >> 12) & 1023) >= t2)) {
            int p = atomicAdd(&s_cnt2, 1);
            if (p < SORTN) { ssort[p] = sigmoidf(cs[i]); isort[p] = ci[i]; }
        }
    }
    __syncthreads();
    const int m = min(s_cnt2, SORTN);
    if (tid < SORTN && tid >= m) { ssort[tid] = -FLT_MAX; isort[tid] = 0x7FFFFFFF; }

    // Bitonic sort 512 (desc sigmoid, asc index on ties)
    for (int k2 = 2; k2 <= SORTN; k2 <<= 1) {
        for (int j = k2 >> 1; j > 0; j >>= 1) {
            __syncthreads();
            if (tid < SORTN) {
                int i = tid, ixj = i ^ j;
                if (ixj > i) {
                    float s1 = ssort[i], s2 = ssort[ixj];
                    int   i1 = isort[i], i2 = isort[ixj];
                    bool pre = (s1 > s2) || (s1 == s2 && i1 <= i2);
                    bool doswap = ((i & k2) == 0) ? (!pre) : pre;
                    if (doswap) {
                        ssort[i] = s2; isort[i] = i2;
                        ssort[ixj] = s1; isort[ixj] = i1;
                    }
                }
            }
        }
    }
    __syncthreads();

    if (tid < KTOP) {
        g_top_s[map * 128 + tid] = ssort[tid];
        g_top_i[map * 128 + tid] = isort[tid];
    }
}

// ---------------------------------------------------------------------------
// Center decode: warp per (b,k) pair; each lane does exactly one gather.
// grid = 400 blocks x 256 threads (8 warps/block -> 3200 pairs).
// ---------------------------------------------------------------------------
__global__ void k_center(const float* __restrict__ wh, const float* __restrict__ kps,
                         const float* __restrict__ reg, const float* __restrict__ scale,
                         float* __restrict__ out) {
    const int pair = blockIdx.x * 8 + (threadIdx.x >> 5);
    const int lane = threadIdx.x & 31;
    if (pair >= BATCH * KTOP) return;
    const int b = pair / KTOP;
    const int k = pair % KTOP;

    const float sc = g_top_s[b * 128 + k];
    const int ind  = g_top_i[b * 128 + k];
    const float ysf = (float)(ind >> 8);
    const float xsf = (float)(ind & 255);

    float g = 0.0f;
    if (lane < 16)       g = kps[((size_t)b * 16 + lane) * HW + ind];
    else if (lane == 16) g = wh[((size_t)b * 2) * HW + ind];
    else if (lane == 17) g = wh[((size_t)b * 2 + 1) * HW + ind];
    else if (lane == 18) g = reg[((size_t)b * 2) * HW + ind];
    else if (lane == 19) g = reg[((size_t)b * 2 + 1) * HW + ind];
    else if (lane < 23)  g = scale[((size_t)b * 3 + (lane - 20)) * HW + ind];

    const unsigned FULL = 0xFFFFFFFFu;
    float w0 = __shfl_sync(FULL, g, 16);
    float w1 = __shfl_sync(FULL, g, 17);
    float r0 = __shfl_sync(FULL, g, 18);
    float r1 = __shfl_sync(FULL, g, 19);
    float xr = xsf + r0, yr = ysf + r1;

    if (lane < 16) {
        out[OFF_DISP + pair * 16 + lane] = g + ((lane & 1) ? ysf : xsf);
    } else if (lane < 20) {
        float bb;
        if      (lane == 16) bb = xr - w0 * 0.5f;
        else if (lane == 17) bb = yr - w1 * 0.5f;
        else if (lane == 18) bb = xr + w0 * 0.5f;
        else                 bb = yr + w1 * 0.5f;
        out[OFF_BBOX + pair * 4 + (lane - 16)] = bb;
    } else if (lane < 23) {
        out[OFF_SCALE + pair * 3 + (lane - 20)] = g;
    } else if (lane == 23) {
        out[OFF_SCORE + pair] = sc;
    } else if (lane == 24) {
        out[OFF_CLS + pair] = 0.0f;
    }
}

// ---------------------------------------------------------------------------
// Joint matching: block = 512 threads handles one (b,j); 16 warps x 7 rounds
// cover the 100 k's; each warp does a 100-candidate argmin with lanes
// splitting candidates 4-ways + 5-stage shuffle reduce ((d, idx) min with
// first-index tie-break = jnp.argmin). grid = 256.
// ---------------------------------------------------------------------------
__global__ __launch_bounds__(512)
void k_joint(const float* __restrict__ hp_offset, float* __restrict__ out) {
    const int blk = blockIdx.x;
    const int b = blk / NJ, j = blk % NJ;
    const int tid = threadIdx.x;
    const int wid = tid >> 5;
    const int lane = tid & 31;

    __shared__ float hx[128], hy[128], hs[128];

    const int map = 32 + b * NJ + j;
    if (tid < KTOP) {
        float s = g_top_s[map * 128 + tid];
        int ind = g_top_i[map * 128 + tid];
        float yy = (float)(ind >> 8);
        float xx = (float)(ind & 255);
        const float* ob = hp_offset + (size_t)b * 2 * HW;
        xx += ob[ind];
        yy += ob[HW + ind];
        bool m = s > 0.1f;
        hs[tid] = m ? s  : -1.0f;
        hx[tid] = m ? xx : -10000.0f;
        hy[tid] = m ? yy : -10000.0f;
    }
    __syncthreads();

    const unsigned FULL = 0xFFFFFFFFu;
    for (int k = wid; k < KTOP; k += 16) {
        const float* od = out + OFF_DISP + (size_t)(b * KTOP + k) * 16;
        float px = od[2 * j], py = od[2 * j + 1];

        // lanes split 100 candidates: c = lane, lane+32, lane+64, lane+96
        float bd = FLT_MAX; int bc = 0x7FFFFFFF;
        #pragma unroll
        for (int q = 0; q < 4; q++) {
            int c = lane + q * 32;
            if (c < KTOP) {
                float dx = px - hx[c], dy = py - hy[c];
                float d = sqrtf(dx * dx + dy * dy);
                if (d < bd || (d == bd && c < bc)) { bd = d; bc = c; }
            }
        }
        // warp reduce: min d, tie -> min index (== first-index argmin)
        #pragma unroll
        for (int off = 16; off > 0; off >>= 1) {
            float od2 = __shfl_down_sync(FULL, bd, off);
            int   oc2 = __shfl_down_sync(FULL, bc, off);
            if (od2 < bd || (od2 == bd && oc2 < bc)) { bd = od2; bc = oc2; }
        }
        bd = __shfl_sync(FULL, bd, 0);
        bc = __shfl_sync(FULL, bc, 0);

        if (lane == 0) {
            float hsg = hs[bc], kx0 = hx[bc], ky0 = hy[bc];
            const float* ob = out + OFF_BBOX + (size_t)(b * KTOP + k) * 4;
            float l = ob[0], t = ob[1], r = ob[2], bo = ob[3];
            float sc = out[OFF_SCORE + b * KTOP + k];
            float diag = fmaxf(bo - t, r - l);

            bool mask = (kx0 < l) || (kx0 > r) || (ky0 < t) || (ky0 > bo) ||
                        (hsg < 0.1f) || (bd > diag * 0.3f);
            float fx = mask ? px : kx0;
            float fy = mask ? py : ky0;
            float* ok = out + OFF_KPS + (size_t)(b * KTOP + k) * 16;
            ok[2 * j] = fx;
            ok[2 * j + 1] = fy;

            bool m2 = (kx0 > 0.8f * l) && (kx0 < 1.2f * r) &&
                      (ky0 > 0.8f * t) && (ky0 < 1.2f * bo) &&
                      (hsg > 0.1f) && (bd < diag * 0.5f) && (sc > 0.1f);
            float* oh = out + OFF_HEAT + (size_t)(b * KTOP + k) * 16;
            oh[2 * j]     = m2 ? kx0 : -10000.0f;
            oh[2 * j + 1] = m2 ? ky0 : -10000.0f;
        }
    }
}

extern "C" void kernel_launch(void* const* d_in, const int* in_sizes, int n_in,
                              void* d_out, int out_size) {
    const float* hm        = (const float*)d_in[0];
    const float* wh        = (const float*)d_in[1];
    const float* kps       = (const float*)d_in[2];
    const float* reg       = (const float*)d_in[3];
    const float* hm_hp     = (const float*)d_in[4];
    const float* hp_offset = (const float*)d_in[5];
    const float* scale     = (const float*)d_in[6];
    float* out = (float*)d_out;
    (void)in_sizes; (void)n_in; (void)out_size;

    k_nms<<<dim3(16, NMAPS), WW>>>(hm, hm_hp);
    k_select<<<NMAPS, 1024>>>();
    k_center<<<(BATCH * KTOP + 7) / 8, 256>>>(wh, kps, reg, scale, out);
    k_joint<<<BATCH * NJ, 512>>>(hp_offset, out);
}